// round 12
// baseline (speedup 1.0000x reference)
#include <cuda_runtime.h>
#include <stdint.h>

// Bidirectional chamfer distance, B=4, N=M=5000, D=3. SINGLE KERNEL.
// d2/2 = hq + hr - q.r. 8 queries/thread as 4 f32x2 packed pairs; refs
// broadcast from SMEM duplicated {x,x,y,y,z,z,h,h}. fma.rn.f32x2 + FMNMX.
// Split-K combine via global atomicMax on COMPLEMENTED monotone float keys
// (identity = 0 = static zero-init -> no init pass; entries reset on consume).
// Last block (threadfence-reduction ticket) sums all mins and writes out.

#define B_    4
#define N_    5000
#define S_    40         // ref split (split-K over refs)
#define CHUNK 125        // N_/S_
#define TPB   128        // threads per block
#define QPT   8          // queries per thread
#define QPB   1024       // queries per block
#define QB    5          // ceil(5000/1024)
#define RPAD  128        // padded refs per chunk
#define NQTOT (2 * B_ * N_)       // 40000
#define NBLK_TOT (QB * 8 * S_)    // 1600

// Per-(dir,b,q) running min, encoded so larger key == smaller value and key 0
// (static zero-init) is the identity (+huge).
__device__ __align__(16) unsigned int g_min[NQTOT];   // zero-initialized
__device__ unsigned int g_done;                       // zero-initialized

__device__ __forceinline__ unsigned int f2key(float v) {
    unsigned int u = __float_as_uint(v);
    unsigned int m = (u & 0x80000000u) ? ~u : (u ^ 0x80000000u);
    return ~m;
}
__device__ __forceinline__ float key2f(unsigned int k) {
    unsigned int m = ~k;
    unsigned int u = (m & 0x80000000u) ? (m ^ 0x80000000u) : ~m;
    return __uint_as_float(u);
}

__global__ __launch_bounds__(TPB) void chamfer_main(const float* __restrict__ pred,
                                                    const float* __restrict__ gt,
                                                    float* __restrict__ out) {
    __shared__ __align__(32) float smf[RPAD * 8];   // 4 KB
    __shared__ unsigned int s_ticket;
    __shared__ float ssum[TPB];

    const int qb  = blockIdx.x;          // query block 0..QB-1
    const int bd  = blockIdx.y;          // dir*B_ + b, 0..7
    const int s   = blockIdx.z;          // ref split 0..S_-1
    const int dir = bd >> 2;             // 0: pred->gt, 1: gt->pred
    const int b   = bd & 3;

    const float* __restrict__ qbase = (dir == 0 ? pred : gt) + b * N_ * 3;
    const float* __restrict__ rbase = (dir == 0 ? gt : pred) + b * N_ * 3 + s * CHUNK * 3;

    const int tid = threadIdx.x;

    // Cooperative load of the ref chunk, duplicated per point for f32x2 ops.
    for (int r = tid; r < RPAD; r += TPB) {
        float gx, gy, gz, h;
        if (r < CHUNK) {
            gx = rbase[r * 3 + 0];
            gy = rbase[r * 3 + 1];
            gz = rbase[r * 3 + 2];
            h  = 0.5f * (gx * gx + gy * gy + gz * gz);
        } else {
            gx = 0.0f; gy = 0.0f; gz = 0.0f; h = 1.0e30f;  // sentinel
        }
        smf[r * 8 + 0] = gx; smf[r * 8 + 1] = gx;
        smf[r * 8 + 2] = gy; smf[r * 8 + 3] = gy;
        smf[r * 8 + 4] = gz; smf[r * 8 + 5] = gz;
        smf[r * 8 + 6] = h;  smf[r * 8 + 7] = h;
    }

    // 8 queries per thread: q_k = qb*QPB + tid + k*TPB, packed pairs (2j, 2j+1).
    int   qi[QPT];
    float hq[QPT];
    uint64_t nx2[4], ny2[4], nz2[4];
#pragma unroll
    for (int j = 0; j < 4; ++j) {
        int k0 = 2 * j, k1 = 2 * j + 1;
        int a = qb * QPB + tid + k0 * TPB;
        int c = qb * QPB + tid + k1 * TPB;
        qi[k0] = a; qi[k1] = c;
        int ac = a < N_ ? a : N_ - 1;
        int cc = c < N_ ? c : N_ - 1;
        float ax = qbase[ac * 3 + 0], ay = qbase[ac * 3 + 1], az = qbase[ac * 3 + 2];
        float bx = qbase[cc * 3 + 0], by = qbase[cc * 3 + 1], bz = qbase[cc * 3 + 2];
        hq[k0] = 0.5f * (ax * ax + ay * ay + az * az);
        hq[k1] = 0.5f * (bx * bx + by * by + bz * bz);
        asm("mov.b64 %0, {%1, %2};" : "=l"(nx2[j]) : "f"(-ax), "f"(-bx));
        asm("mov.b64 %0, {%1, %2};" : "=l"(ny2[j]) : "f"(-ay), "f"(-by));
        asm("mov.b64 %0, {%1, %2};" : "=l"(nz2[j]) : "f"(-az), "f"(-bz));
    }

    __syncthreads();

    uint32_t sbase = (uint32_t)__cvta_generic_to_shared(smf);

    float mn[QPT];
#pragma unroll
    for (int k = 0; k < QPT; ++k) mn[k] = 1.0e30f;

#pragma unroll 4
    for (int p = 0; p < RPAD; ++p) {
        uint64_t rx, ry, rz, rh;
        uint32_t a = sbase + p * 32;
        asm("ld.shared.v2.u64 {%0, %1}, [%2];" : "=l"(rx), "=l"(ry) : "r"(a));
        asm("ld.shared.v2.u64 {%0, %1}, [%2];" : "=l"(rz), "=l"(rh) : "r"(a + 16));
#pragma unroll
        for (int j = 0; j < 4; ++j) {
            float u0, u1;
            asm("{\n\t"
                ".reg .b64 t;\n\t"
                "fma.rn.f32x2 t, %2, %3, %4;\n\t"
                "fma.rn.f32x2 t, %5, %6, t;\n\t"
                "fma.rn.f32x2 t, %7, %8, t;\n\t"
                "mov.b64 {%0, %1}, t;\n\t"
                "}"
                : "=f"(u0), "=f"(u1)
                : "l"(nz2[j]), "l"(rz), "l"(rh),
                  "l"(ny2[j]), "l"(ry),
                  "l"(nx2[j]), "l"(rx));
            mn[2 * j]     = fminf(mn[2 * j], u0);
            mn[2 * j + 1] = fminf(mn[2 * j + 1], u1);
        }
    }

    // Combine across ref chunks: atomicMax on complemented keys (min of v).
    const int base = (dir * B_ + b) * N_;
#pragma unroll
    for (int k = 0; k < QPT; ++k) {
        if (qi[k] < N_) {
            float v = 2.0f * (hq[k] + mn[k]);   // unclamped d2 for this chunk
            atomicMax(&g_min[base + qi[k]], f2key(v));
        }
    }

    // ---- threadfence-reduction: last block finishes the job ----
    __threadfence();
    __syncthreads();
    if (tid == 0) s_ticket = atomicAdd(&g_done, 1u);
    __syncthreads();
    if (s_ticket == NBLK_TOT - 1) {
        __threadfence();                 // acquire: see all blocks' atomics
        float acc = 0.0f;
        uint4* p = (uint4*)g_min;
        const uint4 zero4 = make_uint4(0u, 0u, 0u, 0u);
        for (int i = tid; i < NQTOT / 4; i += TPB) {
            uint4 kk = p[i];
            p[i] = zero4;                // reset to identity for next replay
            acc += fmaxf(key2f(kk.x), 0.0f) + fmaxf(key2f(kk.y), 0.0f) +
                   fmaxf(key2f(kk.z), 0.0f) + fmaxf(key2f(kk.w), 0.0f);
        }
        ssum[tid] = acc;
        __syncthreads();
        for (int off = TPB / 2; off > 0; off >>= 1) {
            if (tid < off) ssum[tid] += ssum[tid + off];
            __syncthreads();
        }
        if (tid == 0) {
            out[0] = ssum[0] * (1.0f / (B_ * N_));
            g_done = 0u;                 // reset for next replay
        }
    }
}

extern "C" void kernel_launch(void* const* d_in, const int* in_sizes, int n_in,
                              void* d_out, int out_size) {
    const float* pred = (const float*)d_in[0];
    const float* gt   = (const float*)d_in[1];
    dim3 grid(QB, 2 * B_, S_);
    chamfer_main<<<grid, TPB>>>(pred, gt, (float*)d_out);
}

// round 13
// speedup vs baseline: 1.2037x; 1.2037x over previous
#include <cuda_runtime.h>
#include <stdint.h>

// Bidirectional chamfer distance, B=4, N=M=5000, D=3.
// d2/2 = hq + hr - q.r. 8 queries/thread as 4 f32x2 packed pairs; refs
// broadcast from SMEM duplicated {x,x,y,y,z,z,h,h} -> ld.shared.v2.u64 gives
// aligned f32x2 operands. fma.rn.f32x2 + scalar FMNMX.
// Split-K combine via global atomicMax on COMPLEMENTED monotone float keys:
// identity = 0 == static zero-init, so no init kernel; finish resets entries
// as it consumes them. Finish: 40 blocks, uint4 loads, last-block final sum
// with PARALLEL __ldcg partial loads + fixed-order tree (deterministic).

#define B_    4
#define N_    5000
#define S_    40         // ref split (split-K over refs)
#define CHUNK 125        // N_/S_
#define TPB   128        // threads per block
#define QPT   8          // queries per thread
#define QPB   1024       // queries per block
#define QB    5          // ceil(5000/1024)
#define RPAD  128        // padded refs per chunk
#define NQTOT (2 * B_ * N_)   // 40000
#define FBLK  40         // finish blocks
#define FTPB  256        // finish threads per block
#define FPER  (NQTOT / FBLK)  // 1000 entries per finish block

// Per-(dir,b,q) running min, encoded so larger key == smaller value and key 0
// (static zero-init) is the identity (+huge).
__device__ __align__(16) unsigned int g_min[NQTOT];   // zero-initialized
__device__ float        g_bsums[FBLK];
__device__ unsigned int g_done;                       // zero-initialized

__device__ __forceinline__ unsigned int f2key(float v) {
    unsigned int u = __float_as_uint(v);
    unsigned int m = (u & 0x80000000u) ? ~u : (u ^ 0x80000000u);
    return ~m;
}
__device__ __forceinline__ float key2f(unsigned int k) {
    unsigned int m = ~k;
    unsigned int u = (m & 0x80000000u) ? (m ^ 0x80000000u) : ~m;
    return __uint_as_float(u);
}

__global__ __launch_bounds__(TPB) void chamfer_main(const float* __restrict__ pred,
                                                    const float* __restrict__ gt) {
    __shared__ __align__(32) float smf[RPAD * 8];   // 4 KB

    const int qb  = blockIdx.x;          // query block 0..QB-1
    const int bd  = blockIdx.y;          // dir*B_ + b, 0..7
    const int s   = blockIdx.z;          // ref split 0..S_-1
    const int dir = bd >> 2;             // 0: pred->gt, 1: gt->pred
    const int b   = bd & 3;

    const float* __restrict__ qbase = (dir == 0 ? pred : gt) + b * N_ * 3;
    const float* __restrict__ rbase = (dir == 0 ? gt : pred) + b * N_ * 3 + s * CHUNK * 3;

    const int tid = threadIdx.x;

    // Cooperative load of the ref chunk, duplicated per point for f32x2 ops.
    for (int r = tid; r < RPAD; r += TPB) {
        float gx, gy, gz, h;
        if (r < CHUNK) {
            gx = rbase[r * 3 + 0];
            gy = rbase[r * 3 + 1];
            gz = rbase[r * 3 + 2];
            h  = 0.5f * (gx * gx + gy * gy + gz * gz);
        } else {
            gx = 0.0f; gy = 0.0f; gz = 0.0f; h = 1.0e30f;  // sentinel
        }
        smf[r * 8 + 0] = gx; smf[r * 8 + 1] = gx;
        smf[r * 8 + 2] = gy; smf[r * 8 + 3] = gy;
        smf[r * 8 + 4] = gz; smf[r * 8 + 5] = gz;
        smf[r * 8 + 6] = h;  smf[r * 8 + 7] = h;
    }

    // 8 queries per thread: q_k = qb*QPB + tid + k*TPB, packed pairs (2j, 2j+1).
    int   qi[QPT];
    float hq[QPT];
    uint64_t nx2[4], ny2[4], nz2[4];
#pragma unroll
    for (int j = 0; j < 4; ++j) {
        int k0 = 2 * j, k1 = 2 * j + 1;
        int a = qb * QPB + tid + k0 * TPB;
        int c = qb * QPB + tid + k1 * TPB;
        qi[k0] = a; qi[k1] = c;
        int ac = a < N_ ? a : N_ - 1;
        int cc = c < N_ ? c : N_ - 1;
        float ax = qbase[ac * 3 + 0], ay = qbase[ac * 3 + 1], az = qbase[ac * 3 + 2];
        float bx = qbase[cc * 3 + 0], by = qbase[cc * 3 + 1], bz = qbase[cc * 3 + 2];
        hq[k0] = 0.5f * (ax * ax + ay * ay + az * az);
        hq[k1] = 0.5f * (bx * bx + by * by + bz * bz);
        asm("mov.b64 %0, {%1, %2};" : "=l"(nx2[j]) : "f"(-ax), "f"(-bx));
        asm("mov.b64 %0, {%1, %2};" : "=l"(ny2[j]) : "f"(-ay), "f"(-by));
        asm("mov.b64 %0, {%1, %2};" : "=l"(nz2[j]) : "f"(-az), "f"(-bz));
    }

    __syncthreads();

    uint32_t sbase = (uint32_t)__cvta_generic_to_shared(smf);

    float mn[QPT];
#pragma unroll
    for (int k = 0; k < QPT; ++k) mn[k] = 1.0e30f;

#pragma unroll 4
    for (int p = 0; p < RPAD; ++p) {
        uint64_t rx, ry, rz, rh;
        uint32_t a = sbase + p * 32;
        asm("ld.shared.v2.u64 {%0, %1}, [%2];" : "=l"(rx), "=l"(ry) : "r"(a));
        asm("ld.shared.v2.u64 {%0, %1}, [%2];" : "=l"(rz), "=l"(rh) : "r"(a + 16));
#pragma unroll
        for (int j = 0; j < 4; ++j) {
            float u0, u1;
            asm("{\n\t"
                ".reg .b64 t;\n\t"
                "fma.rn.f32x2 t, %2, %3, %4;\n\t"
                "fma.rn.f32x2 t, %5, %6, t;\n\t"
                "fma.rn.f32x2 t, %7, %8, t;\n\t"
                "mov.b64 {%0, %1}, t;\n\t"
                "}"
                : "=f"(u0), "=f"(u1)
                : "l"(nz2[j]), "l"(rz), "l"(rh),
                  "l"(ny2[j]), "l"(ry),
                  "l"(nx2[j]), "l"(rx));
            mn[2 * j]     = fminf(mn[2 * j], u0);
            mn[2 * j + 1] = fminf(mn[2 * j + 1], u1);
        }
    }

    // Combine across ref chunks: atomicMax on complemented keys (min of v).
    const int base = (dir * B_ + b) * N_;
#pragma unroll
    for (int k = 0; k < QPT; ++k) {
        if (qi[k] < N_) {
            float v = 2.0f * (hq[k] + mn[k]);   // unclamped d2 for this chunk
            atomicMax(&g_min[base + qi[k]], f2key(v));
        }
    }
}

__global__ __launch_bounds__(FTPB) void chamfer_finish(float* __restrict__ out) {
    __shared__ float ssum[FTPB];
    __shared__ unsigned int s_ticket;
    const int tid = threadIdx.x;

    // Per-block pass: 250 uint4 vectors (1000 entries), reset on consume.
    uint4* p = (uint4*)(g_min + blockIdx.x * FPER);
    const uint4 zero4 = make_uint4(0u, 0u, 0u, 0u);
    float acc = 0.0f;
    for (int i = tid; i < FPER / 4; i += FTPB) {
        uint4 kk = p[i];
        p[i] = zero4;                    // reset to identity for next replay
        acc += fmaxf(key2f(kk.x), 0.0f) + fmaxf(key2f(kk.y), 0.0f) +
               fmaxf(key2f(kk.z), 0.0f) + fmaxf(key2f(kk.w), 0.0f);
    }
    ssum[tid] = acc;
    __syncthreads();
    for (int off = FTPB / 2; off > 0; off >>= 1) {
        if (tid < off) ssum[tid] += ssum[tid + off];
        __syncthreads();
    }
    if (tid == 0) {
        g_bsums[blockIdx.x] = ssum[0];
        __threadfence();                 // release partial before ticket
        s_ticket = atomicAdd(&g_done, 1u);
    }
    __syncthreads();

    if (s_ticket == FBLK - 1) {          // last block: deterministic final sum
        __threadfence();                 // acquire all partials
        float v = (tid < FBLK) ? __ldcg(&g_bsums[tid]) : 0.0f;  // parallel loads
        ssum[tid] = v;
        __syncthreads();
        // Fixed-order tree over 64 padded slots -> deterministic.
        for (int off = 32; off > 0; off >>= 1) {
            if (tid < off) ssum[tid] += ssum[tid + off];
            __syncthreads();
        }
        if (tid == 0) {
            out[0] = ssum[0] * (1.0f / (B_ * N_));
            g_done = 0u;                 // reset for next replay
        }
    }
}

extern "C" void kernel_launch(void* const* d_in, const int* in_sizes, int n_in,
                              void* d_out, int out_size) {
    const float* pred = (const float*)d_in[0];
    const float* gt   = (const float*)d_in[1];
    dim3 grid(QB, 2 * B_, S_);
    chamfer_main<<<grid, TPB>>>(pred, gt);
    chamfer_finish<<<FBLK, FTPB>>>((float*)d_out);
}